// round 5
// baseline (speedup 1.0000x reference)
#include <cuda_runtime.h>
#include <cuda_bf16.h>
#include <math_constants.h>
#include <cstdint>
#include <cstddef>

#define NB 32
#define CC 512
#define PP 1024
#define SS 2048
#define NK 16

#define XSS 136   // x smem tile row stride (bf16), conflict-free for ldmatrix.trans
#define CBS 40    // cb smem tile row stride (bf16)

// static device scratch
__device__ __nv_bfloat16 g_xhi[(size_t)NB * CC * PP];
__device__ __nv_bfloat16 g_xlo[(size_t)NB * CC * PP];
__device__ __nv_bfloat16 g_cbhi[(size_t)SS * CC];
__device__ __nv_bfloat16 g_cblo[(size_t)SS * CC];
__device__ float  g_c2[SS];
__device__ float  g_x2[NB * PP];
__device__ int    g_idx[NB * PP];
__device__ double g_acc_cb;
__device__ double g_acc_commit;

// ---------------------------------------------------------------------------
__device__ __forceinline__ uint32_t cvta_s(const void* p) {
    return (uint32_t)__cvta_generic_to_shared(p);
}
__device__ __forceinline__ void cpa16(uint32_t d, const void* s) {
    asm volatile("cp.async.ca.shared.global [%0],[%1],16;" ::"r"(d), "l"(s));
}
__device__ __forceinline__ void cpcommit() {
    asm volatile("cp.async.commit_group;");
}
__device__ __forceinline__ void cpwait1() {
    asm volatile("cp.async.wait_group 1;");
}
__device__ __forceinline__ void cpwait0() {
    asm volatile("cp.async.wait_group 0;");
}
__device__ __forceinline__ void ldsm4t(uint32_t* d, uint32_t a) {
    asm volatile("ldmatrix.sync.aligned.m8n8.x4.trans.shared.b16 {%0,%1,%2,%3},[%4];"
                 : "=r"(d[0]), "=r"(d[1]), "=r"(d[2]), "=r"(d[3]) : "r"(a));
}
__device__ __forceinline__ void ldsm4(uint32_t* d, uint32_t a) {
    asm volatile("ldmatrix.sync.aligned.m8n8.x4.shared.b16 {%0,%1,%2,%3},[%4];"
                 : "=r"(d[0]), "=r"(d[1]), "=r"(d[2]), "=r"(d[3]) : "r"(a));
}
__device__ __forceinline__ void mma_bf16(float* c, const uint32_t* a, const uint32_t* b) {
    asm volatile("mma.sync.aligned.m16n8k16.row.col.f32.bf16.bf16.f32 "
                 "{%0,%1,%2,%3},{%4,%5,%6,%7},{%8,%9},{%0,%1,%2,%3};"
                 : "+f"(c[0]), "+f"(c[1]), "+f"(c[2]), "+f"(c[3])
                 : "r"(a[0]), "r"(a[1]), "r"(a[2]), "r"(a[3]), "r"(b[0]), "r"(b[1]));
}
__device__ __forceinline__ uint32_t pack_bf2(__nv_bfloat16 a, __nv_bfloat16 b) {
    return (uint32_t)__bfloat16_as_ushort(a) | ((uint32_t)__bfloat16_as_ushort(b) << 16);
}

// ---------------------------------------------------------------------------
__global__ void k_split_x(const float* __restrict__ x) {
    size_t i = ((size_t)blockIdx.x * blockDim.x + threadIdx.x) * 4;
    float4 v = *(const float4*)(x + i);
    __nv_bfloat16 h0 = __float2bfloat16_rn(v.x), h1 = __float2bfloat16_rn(v.y);
    __nv_bfloat16 h2 = __float2bfloat16_rn(v.z), h3 = __float2bfloat16_rn(v.w);
    __nv_bfloat16 l0 = __float2bfloat16_rn(v.x - __bfloat162float(h0));
    __nv_bfloat16 l1 = __float2bfloat16_rn(v.y - __bfloat162float(h1));
    __nv_bfloat16 l2 = __float2bfloat16_rn(v.z - __bfloat162float(h2));
    __nv_bfloat16 l3 = __float2bfloat16_rn(v.w - __bfloat162float(h3));
    *(uint2*)(g_xhi + i) = make_uint2(pack_bf2(h0, h1), pack_bf2(h2, h3));
    *(uint2*)(g_xlo + i) = make_uint2(pack_bf2(l0, l1), pack_bf2(l2, l3));
}

__global__ void k_prep_cb(const float* __restrict__ cb) {
    __shared__ float sm[128];
    int s = blockIdx.x, t = threadIdx.x;
    size_t base = (size_t)s * CC + t * 4;
    float4 v = *(const float4*)(cb + base);
    float a = fmaf(v.x, v.x, fmaf(v.y, v.y, fmaf(v.z, v.z, __fmul_rn(v.w, v.w))));
    __nv_bfloat16 h0 = __float2bfloat16_rn(v.x), h1 = __float2bfloat16_rn(v.y);
    __nv_bfloat16 h2 = __float2bfloat16_rn(v.z), h3 = __float2bfloat16_rn(v.w);
    __nv_bfloat16 l0 = __float2bfloat16_rn(v.x - __bfloat162float(h0));
    __nv_bfloat16 l1 = __float2bfloat16_rn(v.y - __bfloat162float(h1));
    __nv_bfloat16 l2 = __float2bfloat16_rn(v.z - __bfloat162float(h2));
    __nv_bfloat16 l3 = __float2bfloat16_rn(v.w - __bfloat162float(h3));
    *(uint2*)(g_cbhi + base) = make_uint2(pack_bf2(h0, h1), pack_bf2(h2, h3));
    *(uint2*)(g_cblo + base) = make_uint2(pack_bf2(l0, l1), pack_bf2(l2, l3));
    sm[t] = a;
    __syncthreads();
    for (int off = 64; off > 0; off >>= 1) {
        if (t < off) sm[t] += sm[t + off];
        __syncthreads();
    }
    if (t == 0) {
        g_c2[s] = sm[0];
        if (s == 0) { g_acc_cb = 0.0; g_acc_commit = 0.0; }
    }
}

// ---------------------------------------------------------------------------
__global__ void k_x2(const float* __restrict__ x) {
    int pos = blockIdx.x * blockDim.x + threadIdx.x;
    int n = pos >> 10, p = pos & 1023;
    const float* xp = x + (size_t)n * CC * PP + p;
    float a = 0.f;
#pragma unroll 8
    for (int c = 0; c < CC; c++) { float v = xp[(size_t)c * PP]; a = fmaf(v, v, a); }
    g_x2[pos] = a;
}

// ---------------------------------------------------------------------------
// Fused 3-term bf16 tensor-core GEMM + top-NK + argmin, 2-stage cp.async
// pipeline over a global chunk index (16 s-tiles x 16 k-chunks).
// smem (bytes):
#define SM_XH  0                    // 2 x bf16[32][136] = 17408
#define SM_XL  17408                // 17408
#define SM_CH  34816                // 2 x bf16[128][40] = 20480
#define SM_CL  55296                // 20480
#define SM_C2  75776                // float[128]
#define SM_X2  76288                // float[128]
#define SM_DS  76800                // float[64][132] = 33792
#define SM_TOTAL 110592
#define XSTG 8704
#define CSTG 10240

__global__ void __launch_bounds__(256, 2) k_fused(float* __restrict__ out) {
    extern __shared__ __align__(16) char smem[];
    float* c2s = (float*)(smem + SM_C2);
    float* x2s = (float*)(smem + SM_X2);
    float* ds  = (float*)(smem + SM_DS);

    int n = blockIdx.y, p0 = blockIdx.x << 7;
    int tid = threadIdx.x, lid = tid & 31, wid = tid >> 5;
    int wm = wid & 3, wn = wid >> 2;
    int sp = tid & 127, sh = tid >> 7;

    const __nv_bfloat16* xh = g_xhi + (size_t)n * CC * PP;
    const __nv_bfloat16* xl = g_xlo + (size_t)n * CC * PP;

    if (tid < 128) x2s[tid] = g_x2[(n << 10) + p0 + tid];

    // ldmatrix lane address offsets (elements)
    int g = lid >> 3, r = lid & 7;
    int aoff = ((g >> 1) * 8 + r) * XSS + (g & 1) * 8 + wm * 32;
    int boff = ((g >> 1) * 8 + r) * CBS + (g & 1) * 8;

    uint32_t xs_h_b = cvta_s(smem + SM_XH), xs_l_b = cvta_s(smem + SM_XL);
    uint32_t cb_h_b = cvta_s(smem + SM_CH), cb_l_b = cvta_s(smem + SM_CL);

    // cp.async per-thread destinations (stage 0; stage 1 = +XSTG/+CSTG bytes)
    int xrow0 = tid >> 4,          xch0 = (tid & 15) << 3;
    int xrow1 = (tid + 256) >> 4,  xch1 = xch0;
    uint32_t dst_xh0 = xs_h_b + (uint32_t)(xrow0 * XSS + xch0) * 2;
    uint32_t dst_xh1 = xs_h_b + (uint32_t)(xrow1 * XSS + xch1) * 2;
    uint32_t dst_xl0 = xs_l_b + (uint32_t)(xrow0 * XSS + xch0) * 2;
    uint32_t dst_xl1 = xs_l_b + (uint32_t)(xrow1 * XSS + xch1) * 2;
    int crow0 = tid >> 2,        cch0 = (tid & 3) << 3;
    int crow1 = (tid >> 2) + 64, cch1 = cch0;
    uint32_t dst_ch0 = cb_h_b + (uint32_t)(crow0 * CBS + cch0) * 2;
    uint32_t dst_ch1 = cb_h_b + (uint32_t)(crow1 * CBS + cch1) * 2;
    uint32_t dst_cl0 = cb_l_b + (uint32_t)(crow0 * CBS + cch0) * 2;
    uint32_t dst_cl1 = cb_l_b + (uint32_t)(crow1 * CBS + cch1) * 2;

    // issue loads for global chunk G (G in [0,256)); one commit group
    auto issue = [&](int G) {
        int stp = G >> 4, kcp = G & 15, stg = G & 1;
        int k0 = kcp << 5, s0g = stp << 7;
        uint32_t xo = stg ? XSTG : 0u, co = stg ? CSTG : 0u;
        size_t xg0 = (size_t)(k0 + xrow0) * PP + p0 + xch0;
        size_t xg1 = (size_t)(k0 + xrow1) * PP + p0 + xch1;
        cpa16(dst_xh0 + xo, xh + xg0);
        cpa16(dst_xh1 + xo, xh + xg1);
        cpa16(dst_xl0 + xo, xl + xg0);
        cpa16(dst_xl1 + xo, xl + xg1);
        size_t cg0 = (size_t)(s0g + crow0) * CC + k0 + cch0;
        size_t cg1 = (size_t)(s0g + crow1) * CC + k0 + cch1;
        cpa16(dst_ch0 + co, g_cbhi + cg0);
        cpa16(dst_ch1 + co, g_cbhi + cg1);
        cpa16(dst_cl0 + co, g_cblo + cg0);
        cpa16(dst_cl1 + co, g_cblo + cg1);
        cpcommit();
    };

    float topk[NK];
#pragma unroll
    for (int i = 0; i < NK; i++) topk[i] = CUDART_INF_F;
    float minv = CUDART_INF_F;
    int   mini = 0;

    issue(0);
    issue(1);

    for (int st = 0; st < 16; ++st) {
        int s0 = st << 7;
        float acc[2][8][4];
#pragma unroll
        for (int mt = 0; mt < 2; mt++)
#pragma unroll
            for (int nt = 0; nt < 8; nt++)
#pragma unroll
                for (int q = 0; q < 4; q++) acc[mt][nt][q] = 0.f;

        for (int kc = 0; kc < 16; ++kc) {
            int gch = (st << 4) + kc;
            if (gch == 255) cpwait0(); else cpwait1();
            __syncthreads();
            if (kc == 0 && tid < 128) c2s[tid] = g_c2[s0 + tid];

            uint32_t xo = (gch & 1) ? XSTG : 0u, co = (gch & 1) ? CSTG : 0u;
#pragma unroll
            for (int ks = 0; ks < 2; ks++) {
                int kb = ks << 4;
                uint32_t Ah[2][4], Al[2][4];
#pragma unroll
                for (int mt = 0; mt < 2; mt++) {
                    uint32_t ao = (uint32_t)(kb * XSS + aoff + mt * 16) * 2;
                    ldsm4t(Ah[mt], xs_h_b + xo + ao);
                    ldsm4t(Al[mt], xs_l_b + xo + ao);
                }
#pragma unroll
                for (int half = 0; half < 2; half++) {
                    uint32_t Bh[2][4], Bl[2][4];
#pragma unroll
                    for (int bg = 0; bg < 2; bg++) {
                        int n0 = wn * 64 + (half * 2 + bg) * 16;
                        uint32_t bo = (uint32_t)(n0 * CBS + kb + boff) * 2;
                        ldsm4(Bh[bg], cb_h_b + co + bo);
                        ldsm4(Bl[bg], cb_l_b + co + bo);
                    }
#pragma unroll
                    for (int bg = 0; bg < 2; bg++)
#pragma unroll
                        for (int q = 0; q < 2; q++) {
                            int nt = half * 4 + bg * 2 + q;
#pragma unroll
                            for (int mt = 0; mt < 2; mt++) {
                                mma_bf16(acc[mt][nt], Ah[mt], &Bh[bg][q * 2]);
                                mma_bf16(acc[mt][nt], Al[mt], &Bh[bg][q * 2]);
                                mma_bf16(acc[mt][nt], Ah[mt], &Bl[bg][q * 2]);
                            }
                        }
                }
            }
            __syncthreads();
            if (gch + 2 < 256) issue(gch + 2);
        }

        // epilogue + scan in two s-half passes (ds holds 64 rows)
#pragma unroll
        for (int pass = 0; pass < 2; ++pass) {
            if (wn == pass) {
#pragma unroll
                for (int mt = 0; mt < 2; mt++) {
                    int pb = wm * 32 + mt * 16 + (lid >> 2);
                    float x2a = x2s[pb], x2b = x2s[pb + 8];
#pragma unroll
                    for (int nt = 0; nt < 8; nt++) {
                        int sbl = nt * 8 + ((lid & 3) << 1);   // local row 0..63
                        int sb  = wn * 64 + sbl;               // c2 index 0..127
                        float c2a = c2s[sb], c2b = c2s[sb + 1];
                        float* a = acc[mt][nt];
                        ds[sbl * 132 + pb]           = __fadd_rn(__fadd_rn(x2a, c2a), __fmul_rn(-2.0f, a[0]));
                        ds[(sbl + 1) * 132 + pb]     = __fadd_rn(__fadd_rn(x2a, c2b), __fmul_rn(-2.0f, a[1]));
                        ds[sbl * 132 + pb + 8]       = __fadd_rn(__fadd_rn(x2b, c2a), __fmul_rn(-2.0f, a[2]));
                        ds[(sbl + 1) * 132 + pb + 8] = __fadd_rn(__fadd_rn(x2b, c2b), __fmul_rn(-2.0f, a[3]));
                    }
                }
            }
            __syncthreads();
            int rbase = sh << 5;
            int sbase = s0 + (pass << 6);
#pragma unroll 4
            for (int rr = 0; rr < 32; rr++) {
                int rw = rbase + rr;
                float v = ds[rw * 132 + sp];
                int s = sbase + rw;
                if (v < minv) { minv = v; mini = s; }
                if (v < topk[NK - 1]) {
                    topk[NK - 1] = v;
#pragma unroll
                    for (int i = NK - 1; i > 0; --i) {
                        float lo = fminf(topk[i - 1], topk[i]);
                        float hi = fmaxf(topk[i - 1], topk[i]);
                        topk[i - 1] = lo; topk[i] = hi;
                    }
                }
            }
            __syncthreads();
        }
    }

    // merge buffers aliased onto ds (scan finished)
    float*  mtop = ds;
    float*  mval = ds + NK * 128;
    int*    midx = (int*)(mval + 128);
    double* red  = (double*)(midx + 128);

    if (sh == 1) {
#pragma unroll
        for (int k = 0; k < NK; k++) mtop[k * 128 + sp] = topk[k];
        mval[sp] = minv; midx[sp] = mini;
    }
    __syncthreads();
    if (sh == 0) {
        for (int k = 0; k < NK; k++) {
            float v = mtop[k * 128 + sp];
            if (!(v < topk[NK - 1])) break;
            topk[NK - 1] = v;
#pragma unroll
            for (int i = NK - 1; i > 0; --i) {
                float lo = fminf(topk[i - 1], topk[i]);
                float hi = fmaxf(topk[i - 1], topk[i]);
                topk[i - 1] = lo; topk[i] = hi;
            }
        }
        float v2 = mval[sp]; int i2 = midx[sp];
        if (v2 < minv || (v2 == minv && i2 < mini)) { minv = v2; mini = i2; }

        float ws = 0.f;
#pragma unroll
        for (int k = 0; k < NK; k++) ws = fmaf(topk[k], expf(-(float)k), ws);

        int pos = (n << 10) + p0 + sp;
        out[2 + pos] = (float)mini;
        g_idx[pos]   = mini;
        red[sp] = (double)ws;
    }
    __syncthreads();
    for (int off = 64; off > 0; off >>= 1) {
        if (tid < off) red[tid] += red[tid + off];
        __syncthreads();
    }
    if (tid == 0) atomicAdd(&g_acc_cb, red[0]);
}

// ---------------------------------------------------------------------------
__global__ void k_output(const float* __restrict__ x,
                         const float* __restrict__ cb,
                         float* __restrict__ out) {
    int pg = blockIdx.x;
    int n  = pg >> 5;
    int p0 = (pg & 31) << 5;
    int c0 = blockIdx.y << 7;

    __shared__ float sm[32 * 133];
    __shared__ int   sidx[32];
    __shared__ double rs[256];
    int tid = threadIdx.x;

    if (tid < 32) sidx[tid] = g_idx[(n << 10) + p0 + tid];
    __syncthreads();

#pragma unroll
    for (int i = 0; i < 4; i++) {
        int v = tid + (i << 8);
        int rr = v >> 5, c4 = (v & 31) << 2;
        float4 q = *(const float4*)(cb + (size_t)sidx[rr] * CC + c0 + c4);
        float* dst = &sm[rr * 133 + c4];
        dst[0] = q.x; dst[1] = q.y; dst[2] = q.z; dst[3] = q.w;
    }
    __syncthreads();

    int pl = tid & 31;
    int cb8 = tid >> 5;
    float fsum = 0.f;
    float* outv = out + 2 + NB * PP;

#pragma unroll
    for (int i = 0; i < 16; i++) {
        int cl = cb8 + (i << 3);
        float xq = sm[pl * 133 + cl];
        size_t gi = ((size_t)(n * CC + c0 + cl)) * PP + p0 + pl;
        float xv = __ldg(x + gi);
        float df = __fsub_rn(xv, xq);
        fsum = fmaf(df, df, fsum);
        outv[gi] = __fadd_rn(xv, __fsub_rn(xq, xv));
    }

    rs[tid] = (double)fsum;
    __syncthreads();
    for (int off = 128; off > 0; off >>= 1) {
        if (tid < off) rs[tid] += rs[tid + off];
        __syncthreads();
    }
    if (tid == 0) atomicAdd(&g_acc_commit, rs[0]);
}

// ---------------------------------------------------------------------------
__global__ void k_final(float* __restrict__ out) {
    out[0] = (float)(g_acc_cb     / (double)((size_t)NB * SS * PP));
    out[1] = (float)(g_acc_commit / (double)((size_t)NB * CC * PP));
}

// ---------------------------------------------------------------------------
extern "C" void kernel_launch(void* const* d_in, const int* in_sizes, int n_in,
                              void* d_out, int out_size) {
    const float* x  = (const float*)d_in[0];
    const float* cb = (const float*)d_in[1];
    if (n_in >= 2 && in_sizes[0] == SS * CC) {
        x  = (const float*)d_in[1];
        cb = (const float*)d_in[0];
    }
    float* out = (float*)d_out;
    (void)out_size;

    cudaFuncSetAttribute(k_fused, cudaFuncAttributeMaxDynamicSharedMemorySize, SM_TOTAL);

    k_split_x<<<NB * CC * PP / 1024, 256>>>(x);
    k_prep_cb<<<SS, 128>>>(cb);
    k_x2<<<NB * PP / 256, 256>>>(x);
    k_fused<<<dim3(PP / 128, NB), 256, SM_TOTAL>>>(out);
    k_output<<<dim3(1024, 4), 256>>>(x, cb, out);
    k_final<<<1, 1>>>(out);
}

// round 7
// speedup vs baseline: 1.0901x; 1.0901x over previous
#include <cuda_runtime.h>
#include <cuda_bf16.h>
#include <math_constants.h>
#include <cstdint>
#include <cstddef>

#define NB 32
#define CC 512
#define PP 1024
#define SS 2048
#define NK 16

#define XSS 136   // x smem tile row stride (bf16), conflict-free for ldmatrix.trans
#define CBS 40    // cb smem tile row stride (bf16)

// static device scratch (x layout [n][c][p], as in R4/R5)
__device__ __nv_bfloat16 g_xhi[(size_t)NB * CC * PP];
__device__ __nv_bfloat16 g_xlo[(size_t)NB * CC * PP];
__device__ __nv_bfloat16 g_cbhi[(size_t)SS * CC];
__device__ __nv_bfloat16 g_cblo[(size_t)SS * CC];
__device__ float  g_c2[SS];
__device__ float  g_x2[NB * PP];
__device__ int    g_idx[NB * PP];
__device__ double g_acc_cb;
__device__ double g_acc_commit;

// ---------------------------------------------------------------------------
__device__ __forceinline__ uint32_t cvta_s(const void* p) {
    return (uint32_t)__cvta_generic_to_shared(p);
}
__device__ __forceinline__ void cpa16(uint32_t d, const void* s) {
    asm volatile("cp.async.ca.shared.global [%0],[%1],16;" ::"r"(d), "l"(s));
}
__device__ __forceinline__ void cpcommit() {
    asm volatile("cp.async.commit_group;");
}
__device__ __forceinline__ void cpwait1() {
    asm volatile("cp.async.wait_group 1;");
}
__device__ __forceinline__ void cpwait0() {
    asm volatile("cp.async.wait_group 0;");
}
__device__ __forceinline__ void ldsm4t(uint32_t* d, uint32_t a) {
    asm volatile("ldmatrix.sync.aligned.m8n8.x4.trans.shared.b16 {%0,%1,%2,%3},[%4];"
                 : "=r"(d[0]), "=r"(d[1]), "=r"(d[2]), "=r"(d[3]) : "r"(a));
}
__device__ __forceinline__ void ldsm4(uint32_t* d, uint32_t a) {
    asm volatile("ldmatrix.sync.aligned.m8n8.x4.shared.b16 {%0,%1,%2,%3},[%4];"
                 : "=r"(d[0]), "=r"(d[1]), "=r"(d[2]), "=r"(d[3]) : "r"(a));
}
__device__ __forceinline__ void mma_bf16(float* c, const uint32_t* a, const uint32_t* b) {
    asm volatile("mma.sync.aligned.m16n8k16.row.col.f32.bf16.bf16.f32 "
                 "{%0,%1,%2,%3},{%4,%5,%6,%7},{%8,%9},{%0,%1,%2,%3};"
                 : "+f"(c[0]), "+f"(c[1]), "+f"(c[2]), "+f"(c[3])
                 : "r"(a[0]), "r"(a[1]), "r"(a[2]), "r"(a[3]), "r"(b[0]), "r"(b[1]));
}
__device__ __forceinline__ uint32_t pack_bf2(__nv_bfloat16 a, __nv_bfloat16 b) {
    return (uint32_t)__bfloat16_as_ushort(a) | ((uint32_t)__bfloat16_as_ushort(b) << 16);
}
#define BARSYNC(id, cnt) asm volatile("bar.sync %0,%1;" ::"r"(id), "r"(cnt) : "memory")
#define BARARR(id, cnt)  asm volatile("bar.arrive %0,%1;" ::"r"(id), "r"(cnt) : "memory")

// ---------------------------------------------------------------------------
__global__ void k_split_x(const float* __restrict__ x) {
    size_t i = ((size_t)blockIdx.x * blockDim.x + threadIdx.x) * 4;
    float4 v = *(const float4*)(x + i);
    __nv_bfloat16 h0 = __float2bfloat16_rn(v.x), h1 = __float2bfloat16_rn(v.y);
    __nv_bfloat16 h2 = __float2bfloat16_rn(v.z), h3 = __float2bfloat16_rn(v.w);
    __nv_bfloat16 l0 = __float2bfloat16_rn(v.x - __bfloat162float(h0));
    __nv_bfloat16 l1 = __float2bfloat16_rn(v.y - __bfloat162float(h1));
    __nv_bfloat16 l2 = __float2bfloat16_rn(v.z - __bfloat162float(h2));
    __nv_bfloat16 l3 = __float2bfloat16_rn(v.w - __bfloat162float(h3));
    *(uint2*)(g_xhi + i) = make_uint2(pack_bf2(h0, h1), pack_bf2(h2, h3));
    *(uint2*)(g_xlo + i) = make_uint2(pack_bf2(l0, l1), pack_bf2(l2, l3));
}

__global__ void k_prep_cb(const float* __restrict__ cb) {
    __shared__ float sm[128];
    int s = blockIdx.x, t = threadIdx.x;
    size_t base = (size_t)s * CC + t * 4;
    float4 v = *(const float4*)(cb + base);
    float a = fmaf(v.x, v.x, fmaf(v.y, v.y, fmaf(v.z, v.z, __fmul_rn(v.w, v.w))));
    __nv_bfloat16 h0 = __float2bfloat16_rn(v.x), h1 = __float2bfloat16_rn(v.y);
    __nv_bfloat16 h2 = __float2bfloat16_rn(v.z), h3 = __float2bfloat16_rn(v.w);
    __nv_bfloat16 l0 = __float2bfloat16_rn(v.x - __bfloat162float(h0));
    __nv_bfloat16 l1 = __float2bfloat16_rn(v.y - __bfloat162float(h1));
    __nv_bfloat16 l2 = __float2bfloat16_rn(v.z - __bfloat162float(h2));
    __nv_bfloat16 l3 = __float2bfloat16_rn(v.w - __bfloat162float(h3));
    *(uint2*)(g_cbhi + base) = make_uint2(pack_bf2(h0, h1), pack_bf2(h2, h3));
    *(uint2*)(g_cblo + base) = make_uint2(pack_bf2(l0, l1), pack_bf2(l2, l3));
    sm[t] = a;
    __syncthreads();
    for (int off = 64; off > 0; off >>= 1) {
        if (t < off) sm[t] += sm[t + off];
        __syncthreads();
    }
    if (t == 0) {
        g_c2[s] = sm[0];
        if (s == 0) { g_acc_cb = 0.0; g_acc_commit = 0.0; }
    }
}

// ---------------------------------------------------------------------------
__global__ void k_x2(const float* __restrict__ x) {
    int pos = blockIdx.x * blockDim.x + threadIdx.x;
    int n = pos >> 10, p = pos & 1023;
    const float* xp = x + (size_t)n * CC * PP + p;
    float a = 0.f;
#pragma unroll 8
    for (int c = 0; c < CC; c++) { float v = xp[(size_t)c * PP]; a = fmaf(v, v, a); }
    g_x2[pos] = a;
}

// ---------------------------------------------------------------------------
// Fused warp-specialized kernel: warps 0-7 (256 thr) = GEMM producers,
// warps 8-11 (128 thr) = selection consumers (1 p-lane per thread).
// Named barriers: 1 = ds full (prod arrive / cons sync),
//                 2 = ds free (cons arrive / prod sync), 3 = producer-internal.
// smem (bytes):
#define SM_XH   0        // 2 x bf16[32][136] = 17408
#define SM_XL   17408    // 17408
#define SM_CH   34816    // 2 x bf16[128][40] = 20480
#define SM_CL   55296    // 20480
#define SM_C2A  75776    // float[2048] = 8192
#define SM_DS   83968    // float[128][132] = 67584 (raw xc accumulators)
#define SM_RED  151552   // double[128] = 1024
#define SM_TOTAL 152576
#define XSTG 8704
#define CSTG 10240

__global__ void __launch_bounds__(384, 1) k_fused(float* __restrict__ out) {
    extern __shared__ __align__(16) char smem[];
    float*  c2all = (float*)(smem + SM_C2A);
    float*  ds    = (float*)(smem + SM_DS);
    double* red   = (double*)(smem + SM_RED);

    int n = blockIdx.y, p0 = blockIdx.x << 7;
    int tid = threadIdx.x;

    for (int i = tid; i < SS; i += 384) c2all[i] = g_c2[i];
    __syncthreads();

    if (tid < 256) {
        // ================= GEMM producers =================
        int lid = tid & 31, wid = tid >> 5;
        int wm = wid & 3, wn = wid >> 2;

        const __nv_bfloat16* xh = g_xhi + (size_t)n * CC * PP;
        const __nv_bfloat16* xl = g_xlo + (size_t)n * CC * PP;

        int g = lid >> 3, r = lid & 7;
        int aoff = ((g >> 1) * 8 + r) * XSS + (g & 1) * 8 + wm * 32;
        int boff = ((g >> 1) * 8 + r) * CBS + (g & 1) * 8;

        uint32_t xs_h_b = cvta_s(smem + SM_XH), xs_l_b = cvta_s(smem + SM_XL);
        uint32_t cb_h_b = cvta_s(smem + SM_CH), cb_l_b = cvta_s(smem + SM_CL);

        int xrow0 = tid >> 4,          xch0 = (tid & 15) << 3;
        int xrow1 = (tid + 256) >> 4,  xch1 = xch0;
        uint32_t dst_xh0 = xs_h_b + (uint32_t)(xrow0 * XSS + xch0) * 2;
        uint32_t dst_xh1 = xs_h_b + (uint32_t)(xrow1 * XSS + xch1) * 2;
        uint32_t dst_xl0 = xs_l_b + (uint32_t)(xrow0 * XSS + xch0) * 2;
        uint32_t dst_xl1 = xs_l_b + (uint32_t)(xrow1 * XSS + xch1) * 2;
        int crow0 = tid >> 2,        cch0 = (tid & 3) << 3;
        int crow1 = (tid >> 2) + 64, cch1 = cch0;
        uint32_t dst_ch0 = cb_h_b + (uint32_t)(crow0 * CBS + cch0) * 2;
        uint32_t dst_ch1 = cb_h_b + (uint32_t)(crow1 * CBS + cch1) * 2;
        uint32_t dst_cl0 = cb_l_b + (uint32_t)(crow0 * CBS + cch0) * 2;
        uint32_t dst_cl1 = cb_l_b + (uint32_t)(crow1 * CBS + cch1) * 2;

        auto issue = [&](int G) {
            int stp = G >> 4, kcp = G & 15, stg = G & 1;
            int k0 = kcp << 5, s0g = stp << 7;
            uint32_t xo = stg ? XSTG : 0u, co = stg ? CSTG : 0u;
            size_t xg0 = (size_t)(k0 + xrow0) * PP + p0 + xch0;
            size_t xg1 = (size_t)(k0 + xrow1) * PP + p0 + xch1;
            cpa16(dst_xh0 + xo, xh + xg0);
            cpa16(dst_xh1 + xo, xh + xg1);
            cpa16(dst_xl0 + xo, xl + xg0);
            cpa16(dst_xl1 + xo, xl + xg1);
            size_t cg0 = (size_t)(s0g + crow0) * CC + k0 + cch0;
            size_t cg1 = (size_t)(s0g + crow1) * CC + k0 + cch1;
            cpa16(dst_ch0 + co, g_cbhi + cg0);
            cpa16(dst_ch1 + co, g_cbhi + cg1);
            cpa16(dst_cl0 + co, g_cblo + cg0);
            cpa16(dst_cl1 + co, g_cblo + cg1);
            cpcommit();
        };

        issue(0);
        issue(1);

        for (int st = 0; st < 16; ++st) {
            float acc[2][8][4];
#pragma unroll
            for (int mt = 0; mt < 2; mt++)
#pragma unroll
                for (int nt = 0; nt < 8; nt++)
#pragma unroll
                    for (int q = 0; q < 4; q++) acc[mt][nt][q] = 0.f;

            for (int kc = 0; kc < 16; ++kc) {
                int gch = (st << 4) + kc;
                if (gch == 255) cpwait0(); else cpwait1();
                BARSYNC(3, 256);

                uint32_t xo = (gch & 1) ? XSTG : 0u, co = (gch & 1) ? CSTG : 0u;
#pragma unroll
                for (int ks = 0; ks < 2; ks++) {
                    int kb = ks << 4;
                    uint32_t Ah[2][4], Al[2][4];
#pragma unroll
                    for (int mt = 0; mt < 2; mt++) {
                        uint32_t ao = (uint32_t)(kb * XSS + aoff + mt * 16) * 2;
                        ldsm4t(Ah[mt], xs_h_b + xo + ao);
                        ldsm4t(Al[mt], xs_l_b + xo + ao);
                    }
#pragma unroll
                    for (int half = 0; half < 2; half++) {
                        uint32_t Bh[2][4], Bl[2][4];
#pragma unroll
                        for (int bg = 0; bg < 2; bg++) {
                            int n0 = wn * 64 + (half * 2 + bg) * 16;
                            uint32_t bo = (uint32_t)(n0 * CBS + kb + boff) * 2;
                            ldsm4(Bh[bg], cb_h_b + co + bo);
                            ldsm4(Bl[bg], cb_l_b + co + bo);
                        }
#pragma unroll
                        for (int bg = 0; bg < 2; bg++)
#pragma unroll
                            for (int q = 0; q < 2; q++) {
                                int nt = half * 4 + bg * 2 + q;
#pragma unroll
                                for (int mt = 0; mt < 2; mt++) {
                                    mma_bf16(acc[mt][nt], Ah[mt], &Bh[bg][q * 2]);
                                    mma_bf16(acc[mt][nt], Al[mt], &Bh[bg][q * 2]);
                                    mma_bf16(acc[mt][nt], Ah[mt], &Bl[bg][q * 2]);
                                }
                            }
                    }
                }
                BARSYNC(3, 256);
                if (gch + 2 < 256) issue(gch + 2);
            }

            // hand off raw accumulators (xc) through ds
            if (st > 0) BARSYNC(2, 384);   // wait: consumers done with tile st-1
#pragma unroll
            for (int mt = 0; mt < 2; mt++) {
                int pb = wm * 32 + mt * 16 + (lid >> 2);
#pragma unroll
                for (int nt = 0; nt < 8; nt++) {
                    int sb = wn * 64 + nt * 8 + ((lid & 3) << 1);
                    float* a = acc[mt][nt];
                    ds[sb * 132 + pb]           = a[0];
                    ds[(sb + 1) * 132 + pb]     = a[1];
                    ds[sb * 132 + pb + 8]       = a[2];
                    ds[(sb + 1) * 132 + pb + 8] = a[3];
                }
            }
            BARARR(1, 384);                // signal: tile st ready
        }
    } else {
        // ================= selection consumers =================
        int sp = tid - 256;                // p-lane 0..127
        int pos = (n << 10) + p0 + sp;
        float x2p = g_x2[pos];

        float topk[NK];
#pragma unroll
        for (int i = 0; i < NK; i++) topk[i] = CUDART_INF_F;
        float minv = CUDART_INF_F;
        int   mini = 0;

        for (int st = 0; st < 16; ++st) {
            BARSYNC(1, 384);               // wait: tile st ready
            int s0 = st << 7;
#pragma unroll 4
            for (int rr = 0; rr < 128; rr++) {
                float a = ds[rr * 132 + sp];
                float v = __fadd_rn(__fadd_rn(x2p, c2all[s0 + rr]),
                                    __fmul_rn(-2.0f, a));
                int s = s0 + rr;
                if (v < minv) { minv = v; mini = s; }
                if (v < topk[NK - 1]) {
                    topk[NK - 1] = v;
#pragma unroll
                    for (int i = NK - 1; i > 0; --i) {
                        float lo = fminf(topk[i - 1], topk[i]);
                        float hi = fmaxf(topk[i - 1], topk[i]);
                        topk[i - 1] = lo; topk[i] = hi;
                    }
                }
            }
            BARARR(2, 384);                // signal: ds free
        }

        float ws = 0.f;
#pragma unroll
        for (int k = 0; k < NK; k++) ws = fmaf(topk[k], expf(-(float)k), ws);
        out[2 + pos] = (float)mini;
        g_idx[pos]   = mini;
        red[sp] = (double)ws;
    }

    __syncthreads();
    for (int off = 64; off > 0; off >>= 1) {
        if (tid < off) red[tid] += red[tid + off];
        __syncthreads();
    }
    if (tid == 0) atomicAdd(&g_acc_cb, red[0]);
}

// ---------------------------------------------------------------------------
__global__ void k_output(const float* __restrict__ x,
                         const float* __restrict__ cb,
                         float* __restrict__ out) {
    int pg = blockIdx.x;
    int n  = pg >> 5;
    int p0 = (pg & 31) << 5;
    int c0 = blockIdx.y << 7;

    __shared__ float sm[32 * 133];
    __shared__ int   sidx[32];
    __shared__ double rs[256];
    int tid = threadIdx.x;

    if (tid < 32) sidx[tid] = g_idx[(n << 10) + p0 + tid];
    __syncthreads();

#pragma unroll
    for (int i = 0; i < 4; i++) {
        int v = tid + (i << 8);
        int rr = v >> 5, c4 = (v & 31) << 2;
        float4 q = *(const float4*)(cb + (size_t)sidx[rr] * CC + c0 + c4);
        float* dst = &sm[rr * 133 + c4];
        dst[0] = q.x; dst[1] = q.y; dst[2] = q.z; dst[3] = q.w;
    }
    __syncthreads();

    int pl = tid & 31;
    int cb8 = tid >> 5;
    float fsum = 0.f;
    float* outv = out + 2 + NB * PP;

#pragma unroll
    for (int i = 0; i < 16; i++) {
        int cl = cb8 + (i << 3);
        float xq = sm[pl * 133 + cl];
        size_t gi = ((size_t)(n * CC + c0 + cl)) * PP + p0 + pl;
        float xv = __ldg(x + gi);
        float df = __fsub_rn(xv, xq);
        fsum = fmaf(df, df, fsum);
        outv[gi] = __fadd_rn(xv, __fsub_rn(xq, xv));
    }

    rs[tid] = (double)fsum;
    __syncthreads();
    for (int off = 128; off > 0; off >>= 1) {
        if (tid < off) rs[tid] += rs[tid + off];
        __syncthreads();
    }
    if (tid == 0) atomicAdd(&g_acc_commit, rs[0]);
}

// ---------------------------------------------------------------------------
__global__ void k_final(float* __restrict__ out) {
    out[0] = (float)(g_acc_cb     / (double)((size_t)NB * SS * PP));
    out[1] = (float)(g_acc_commit / (double)((size_t)NB * CC * PP));
}

// ---------------------------------------------------------------------------
extern "C" void kernel_launch(void* const* d_in, const int* in_sizes, int n_in,
                              void* d_out, int out_size) {
    const float* x  = (const float*)d_in[0];
    const float* cb = (const float*)d_in[1];
    if (n_in >= 2 && in_sizes[0] == SS * CC) {
        x  = (const float*)d_in[1];
        cb = (const float*)d_in[0];
    }
    float* out = (float*)d_out;
    (void)out_size;

    cudaFuncSetAttribute(k_fused, cudaFuncAttributeMaxDynamicSharedMemorySize, SM_TOTAL);

    k_split_x<<<NB * CC * PP / 1024, 256>>>(x);
    k_prep_cb<<<SS, 128>>>(cb);
    k_x2<<<NB * PP / 256, 256>>>(x);
    k_fused<<<dim3(PP / 128, NB), 384, SM_TOTAL>>>(out);
    k_output<<<dim3(1024, 4), 256>>>(x, cb, out);
    k_final<<<1, 1>>>(out);
}